// round 3
// baseline (speedup 1.0000x reference)
#include <cuda_runtime.h>
#include <math.h>

// ---------------- problem constants ----------------
#define BSZ   64
#define HID   512
#define G3    1536          // 3*HID
#define LEN   400           // encoder length
#define TOUT  100           // decoder steps
#define VOC   50000
#define LMAX  400
#define MROWS (TOUT*BSZ)    // 6400 decoder rows
#define NCB   391           // phase-C column blocks: ceil(50000/128)
#define NBLK  148           // persistent grid size (<= SM count, all co-resident)

// ---------------- device scratch (static, allocation-free) ----------------
__device__ float g_encGx[(size_t)LEN*BSZ*G3];    // x-gates for encoder, incl bias
__device__ float g_attnx[(size_t)TOUT*BSZ*LMAX]; // x-part of attn logits, incl attn_b
__device__ float g_combx[(size_t)TOUT*BSZ*HID];  // x-part of combine, incl comb_b
__device__ int   g_dectok[TOUT*BSZ];
__device__ float g_h[BSZ*HID];                   // current hidden
__device__ float g_enc0[BSZ*HID];                // encoder output at t=0
__device__ float g_enc0W[BSZ*HID];               // enc0 @ comb_W[:,H:]^T
__device__ float g_part[4*BSZ*G3];               // K-split partials for step GEMMs
__device__ float g_a0[BSZ];
__device__ float g_c[BSZ*HID];
__device__ float g_H2[(size_t)MROWS*HID];        // all decoder hiddens
__device__ float g_pm[(size_t)MROWS*NCB];        // per-tile row max
__device__ float g_ps[(size_t)MROWS*NCB];        // per-tile row sumexp
__device__ float g_tgtlog[MROWS];                // logits at target index
__device__ float g_lossp[32];                    // per-block loss partials

// grid barrier state (persists across replays; sense-reversal via generation)
__device__ unsigned g_barcnt;
__device__ unsigned g_bargen;

__device__ __forceinline__ float sigmf(float x) { return 1.0f / (1.0f + expf(-x)); }

__device__ __forceinline__ void gridbar(unsigned &gen)
{
    __syncthreads();
    if (threadIdx.x == 0) {
        __threadfence();
        unsigned prev = atomicAdd(&g_barcnt, 1u);
        if (prev == NBLK - 1u) {
            atomicExch(&g_barcnt, 0u);
            __threadfence();
            atomicAdd(&g_bargen, 1u);
        } else {
            while (atomicAdd(&g_bargen, 0u) == gen) __nanosleep(64);
        }
        gen++;
    }
    __syncthreads();
}

// ---------------- init: zero h, build decoder tokens ----------------
__global__ void k_init(const int* __restrict__ tgt)
{
    int i = blockIdx.x * 256 + threadIdx.x;      // covers 32768
    if (i < BSZ*HID) g_h[i] = 0.0f;
    if (i < TOUT*BSZ) {
        int t = i / BSZ, b = i % BSZ;
        g_dectok[i] = (t == 0) ? 1 : tgt[(t-1)*BSZ + b];
    }
}

// ---------------- generic big SGEMM: C[M,N] = A'[M,K] @ B[N,(ldb)]^T + bias ----------------
template<bool GATHER>
__global__ void __launch_bounds__(256)
k_sgemm128(const float* __restrict__ A,
           const int*  __restrict__ gidx,
           const float* __restrict__ Bw, int ldb,
           const float* __restrict__ bias,
           float* __restrict__ C,
           int M, int N, int K)
{
    __shared__ __align__(16) float sA[16][128];
    __shared__ __align__(16) float sB[16][128];
    const int tid = threadIdx.x;
    const int bm = blockIdx.y * 128;
    const int bn = blockIdx.x * 128;
    const int tx = tid & 15;
    const int ty = tid >> 4;
    const int lr = tid >> 2;          // 0..63
    const int lk = (tid & 3) << 2;    // 0,4,8,12

    int m0 = bm + lr, m1 = m0 + 64;
    const bool mv0 = m0 < M, mv1 = m1 < M;
    size_t ar0, ar1;
    if (GATHER) {
        ar0 = (size_t)(mv0 ? gidx[m0] : gidx[0]) * (size_t)K;
        ar1 = (size_t)(mv1 ? gidx[m1] : gidx[0]) * (size_t)K;
    } else {
        ar0 = (size_t)(mv0 ? m0 : 0) * (size_t)K;
        ar1 = (size_t)(mv1 ? m1 : 0) * (size_t)K;
    }
    int n0 = bn + lr, n1 = n0 + 64;
    size_t br0 = (size_t)(n0 < N ? n0 : 0) * (size_t)ldb;
    size_t br1 = (size_t)(n1 < N ? n1 : 0) * (size_t)ldb;

    float acc[8][8];
#pragma unroll
    for (int i = 0; i < 8; i++)
#pragma unroll
        for (int j = 0; j < 8; j++) acc[i][j] = 0.0f;

    for (int kb = 0; kb < K; kb += 16) {
        float4 a0 = *(const float4*)(A  + ar0 + kb + lk);
        float4 a1 = *(const float4*)(A  + ar1 + kb + lk);
        float4 b0 = *(const float4*)(Bw + br0 + kb + lk);
        float4 b1 = *(const float4*)(Bw + br1 + kb + lk);
        __syncthreads();
        sA[lk+0][lr] = a0.x; sA[lk+1][lr] = a0.y; sA[lk+2][lr] = a0.z; sA[lk+3][lr] = a0.w;
        sA[lk+0][lr+64] = a1.x; sA[lk+1][lr+64] = a1.y; sA[lk+2][lr+64] = a1.z; sA[lk+3][lr+64] = a1.w;
        sB[lk+0][lr] = b0.x; sB[lk+1][lr] = b0.y; sB[lk+2][lr] = b0.z; sB[lk+3][lr] = b0.w;
        sB[lk+0][lr+64] = b1.x; sB[lk+1][lr+64] = b1.y; sB[lk+2][lr+64] = b1.z; sB[lk+3][lr+64] = b1.w;
        __syncthreads();
#pragma unroll
        for (int k = 0; k < 16; k++) {
            float4 pa0 = *(const float4*)(&sA[k][ty*8]);
            float4 pa1 = *(const float4*)(&sA[k][ty*8+4]);
            float4 pb0 = *(const float4*)(&sB[k][tx*8]);
            float4 pb1 = *(const float4*)(&sB[k][tx*8+4]);
            float av[8] = {pa0.x,pa0.y,pa0.z,pa0.w,pa1.x,pa1.y,pa1.z,pa1.w};
            float bv[8] = {pb0.x,pb0.y,pb0.z,pb0.w,pb1.x,pb1.y,pb1.z,pb1.w};
#pragma unroll
            for (int i = 0; i < 8; i++)
#pragma unroll
                for (int j = 0; j < 8; j++)
                    acc[i][j] += av[i] * bv[j];
        }
    }

#pragma unroll
    for (int i = 0; i < 8; i++) {
        int m = bm + ty*8 + i;
        if (m < M) {
            float* crow = C + (size_t)m * (size_t)N;
#pragma unroll
            for (int j = 0; j < 8; j++) {
                int n = bn + tx*8 + j;
                if (n < N) crow[n] = acc[i][j] + (bias ? bias[n] : 0.0f);
            }
        }
    }
}

// ---------------- per-task 64x64 step-GEMM helper (uses 8KB of sm) ----------------
// C tile [64 x 64] at column bn: Cp[row*G3 + bn + col] = sum_{k in [kbase, kbase+Kloc)} A[row,k]*Bm[bn+col,k]
__device__ __forceinline__ void step_gemm_task(
    const float* __restrict__ A, const float* __restrict__ Bm,
    int nb, int kbase, int Kloc, float* __restrict__ Cp, float* sm)
{
    float* sA = sm;           // [16][64]
    float* sB = sm + 1024;    // [16][64]
    const int tid = threadIdx.x;
    const int tx = tid & 15, ty = tid >> 4;
    const int lr = tid >> 2, lk = (tid & 3) << 2;
    const int bn = nb * 64;

    float acc[4][4];
#pragma unroll
    for (int i = 0; i < 4; i++)
#pragma unroll
        for (int j = 0; j < 4; j++) acc[i][j] = 0.0f;

    for (int kb = 0; kb < Kloc; kb += 16) {
        int kg = kbase + kb;
        float4 av = *(const float4*)(A  + lr*HID + kg + lk);
        float4 bv = *(const float4*)(Bm + (size_t)(bn + lr)*HID + kg + lk);
        __syncthreads();
        sA[(lk+0)*64+lr] = av.x; sA[(lk+1)*64+lr] = av.y; sA[(lk+2)*64+lr] = av.z; sA[(lk+3)*64+lr] = av.w;
        sB[(lk+0)*64+lr] = bv.x; sB[(lk+1)*64+lr] = bv.y; sB[(lk+2)*64+lr] = bv.z; sB[(lk+3)*64+lr] = bv.w;
        __syncthreads();
#pragma unroll
        for (int k = 0; k < 16; k++) {
            float4 pa = *(const float4*)(sA + k*64 + ty*4);
            float4 pb = *(const float4*)(sB + k*64 + tx*4);
            float a4[4] = {pa.x, pa.y, pa.z, pa.w};
            float b4[4] = {pb.x, pb.y, pb.z, pb.w};
#pragma unroll
            for (int i = 0; i < 4; i++)
#pragma unroll
                for (int j = 0; j < 4; j++)
                    acc[i][j] += a4[i] * b4[j];
        }
    }
    __syncthreads();
#pragma unroll
    for (int i = 0; i < 4; i++)
#pragma unroll
        for (int j = 0; j < 4; j++)
            Cp[(ty*4 + i)*G3 + bn + tx*4 + j] = acc[i][j];
}

// ---------------- persistent encoder: 400 GRU steps in one launch ----------------
__global__ void __launch_bounds__(256)
k_encoder(const float* __restrict__ Whh, const float* __restrict__ bhh)
{
    __shared__ __align__(16) float sm[2048];
    unsigned gen = 0;
    if (threadIdx.x == 0) gen = atomicAdd(&g_bargen, 0u);
    const int blk = blockIdx.x;

    for (int t = 0; t < LEN; t++) {
        // h @ Whh^T : 24 n-tiles x 4 K-splits = 96 tasks
        if (blk < 96) {
            int ks = blk / 24, nb = blk % 24;
            step_gemm_task(g_h, Whh, nb, ks*128, 128, g_part + (size_t)ks*BSZ*G3, sm);
        }
        gridbar(gen);
        // gate fuse
        if (blk < 128) {
            int idx = blk*256 + threadIdx.x;        // 0..32767
            int b = idx >> 9, j = idx & 511;
            int base = b * G3;
            float hr = bhh[j], hz = bhh[j+512], hn = bhh[j+1024];
#pragma unroll
            for (int s = 0; s < 4; s++) {
                const float* p = g_part + (size_t)s * BSZ * G3 + base;
                hr += p[j]; hz += p[j+512]; hn += p[j+1024];
            }
            const float* gx = g_encGx + ((size_t)t*BSZ + b) * G3;
            float r = sigmf(gx[j] + hr);
            float z = sigmf(gx[j+512] + hz);
            float n = tanhf(gx[j+1024] + r * hn);
            float hp = g_h[idx];
            float h2 = (1.0f - z) * n + z * hp;
            g_h[idx] = h2;
            if (t == 0) g_enc0[idx] = h2;
        }
        gridbar(gen);
    }
}

// ---------------- persistent decoder: 100 steps in one launch ----------------
__global__ void __launch_bounds__(256)
k_decoder(const float* __restrict__ attn_W,
          const float* __restrict__ dec_Wih, const float* __restrict__ dec_Whh,
          const float* __restrict__ bih, const float* __restrict__ bhh)
{
    __shared__ __align__(16) float sm[2048];
    unsigned gen = 0;
    if (threadIdx.x == 0) gen = atomicAdd(&g_bargen, 0u);
    const int blk = blockIdx.x;
    const int tid = threadIdx.x;

    for (int t = 0; t < TOUT; t++) {
        // --- attention: a0[b] = softmax over LMAX of (attnx + h-part)[0]
        if (blk < 64) {
            const int b = blk;
            float* sh = sm;            // 512
            float* slg = sm + 512;     // 400
            float* sred = sm + 912;    // 256
            sh[tid]       = g_h[b*HID + tid];
            sh[tid + 256] = g_h[b*HID + tid + 256];
            __syncthreads();
            const float4* h4 = (const float4*)sh;
            for (int l = tid; l < LMAX; l += 256) {
                const float4* w4 = (const float4*)(attn_W + (size_t)l*1024 + 512);
                float s = 0.0f;
#pragma unroll 4
                for (int k = 0; k < 128; k++) {
                    float4 w = w4[k], h = h4[k];
                    s += w.x*h.x + w.y*h.y + w.z*h.z + w.w*h.w;
                }
                slg[l] = g_attnx[((size_t)t*BSZ + b)*LMAX + l] + s;
            }
            __syncthreads();
            float lm = -1e30f;
            for (int l = tid; l < LMAX; l += 256) lm = fmaxf(lm, slg[l]);
            sred[tid] = lm; __syncthreads();
            for (int off = 128; off > 0; off >>= 1) {
                if (tid < off) sred[tid] = fmaxf(sred[tid], sred[tid+off]);
                __syncthreads();
            }
            float mx = sred[0];
            __syncthreads();
            float ls = 0.0f;
            for (int l = tid; l < LMAX; l += 256) ls += expf(slg[l] - mx);
            sred[tid] = ls; __syncthreads();
            for (int off = 128; off > 0; off >>= 1) {
                if (tid < off) sred[tid] += sred[tid+off];
                __syncthreads();
            }
            if (tid == 0) g_a0[b] = expf(slg[0] - mx) / sred[0];
        }
        gridbar(gen);
        // --- combine: c = relu(combx + a0*enc0W)
        if (blk < 128) {
            int idx = blk*256 + tid;
            int b = idx >> 9, j = idx & 511;
            float v = g_combx[((size_t)t*BSZ + b)*HID + j] + g_a0[b] * g_enc0W[idx];
            g_c[idx] = v > 0.0f ? v : 0.0f;
        }
        gridbar(gen);
        // --- two 64x1536x512 GEMMs: (Wih on c) tasks 0..47, (Whh on h) tasks 48..95
        if (blk < 96) {
            int group = blk / 48, rem = blk % 48;
            int nb = rem % 24, ks = rem / 24;
            const float* A  = group ? g_h : g_c;
            const float* Bm = group ? dec_Whh : dec_Wih;
            step_gemm_task(A, Bm, nb, ks*256, 256,
                           g_part + (size_t)(group*2 + ks)*BSZ*G3, sm);
        }
        gridbar(gen);
        // --- gate fuse (writes g_h and g_H2[t])
        if (blk < 128) {
            int idx = blk*256 + tid;
            int b = idx >> 9, j = idx & 511;
            int base = b * G3;
            float ir = bih[j], iz = bih[j+512], in = bih[j+1024];
            float hr = bhh[j], hz = bhh[j+512], hn = bhh[j+1024];
#pragma unroll
            for (int s = 0; s < 2; s++) {
                const float* pi = g_part + (size_t)s * BSZ * G3 + base;
                const float* ph = g_part + (size_t)(s+2) * BSZ * G3 + base;
                ir += pi[j]; iz += pi[j+512]; in += pi[j+1024];
                hr += ph[j]; hz += ph[j+512]; hn += ph[j+1024];
            }
            float r = sigmf(ir + hr);
            float z = sigmf(iz + hz);
            float n = tanhf(in + r * hn);
            float hp = g_h[idx];
            float h2 = (1.0f - z) * n + z * hp;
            g_h[idx] = h2;
            g_H2[(size_t)t*BSZ*HID + idx] = h2;
        }
        gridbar(gen);
    }
}

// ---------------- phase C: H2[6400,512] @ out_W^T + out_b, fused logsumexp partials ----------------
__global__ void __launch_bounds__(256)
k_outgemm(const float* __restrict__ Bw,     // out_W [V,512]
          const float* __restrict__ ob,     // out_b [V]
          const int*   __restrict__ tgt)    // target flat [6400]
{
    __shared__ __align__(16) float sA[16][128];
    __shared__ __align__(16) float sB[16][128];
    __shared__ float red[128][17];
    const int tid = threadIdx.x;
    const int bm = blockIdx.y * 128;
    const int bn = blockIdx.x * 128;
    const int tx = tid & 15, ty = tid >> 4;
    const int lr = tid >> 2, lk = (tid & 3) << 2;

    size_t ar0 = (size_t)(bm + lr) * HID;
    size_t ar1 = (size_t)(bm + lr + 64) * HID;
    int n0 = bn + lr, n1 = n0 + 64;
    size_t br0 = (size_t)(n0 < VOC ? n0 : 0) * HID;
    size_t br1 = (size_t)(n1 < VOC ? n1 : 0) * HID;

    float acc[8][8];
#pragma unroll
    for (int i = 0; i < 8; i++)
#pragma unroll
        for (int j = 0; j < 8; j++) acc[i][j] = 0.0f;

    for (int kb = 0; kb < HID; kb += 16) {
        float4 a0 = *(const float4*)(g_H2 + ar0 + kb + lk);
        float4 a1 = *(const float4*)(g_H2 + ar1 + kb + lk);
        float4 b0 = *(const float4*)(Bw + br0 + kb + lk);
        float4 b1 = *(const float4*)(Bw + br1 + kb + lk);
        __syncthreads();
        sA[lk+0][lr] = a0.x; sA[lk+1][lr] = a0.y; sA[lk+2][lr] = a0.z; sA[lk+3][lr] = a0.w;
        sA[lk+0][lr+64] = a1.x; sA[lk+1][lr+64] = a1.y; sA[lk+2][lr+64] = a1.z; sA[lk+3][lr+64] = a1.w;
        sB[lk+0][lr] = b0.x; sB[lk+1][lr] = b0.y; sB[lk+2][lr] = b0.z; sB[lk+3][lr] = b0.w;
        sB[lk+0][lr+64] = b1.x; sB[lk+1][lr+64] = b1.y; sB[lk+2][lr+64] = b1.z; sB[lk+3][lr+64] = b1.w;
        __syncthreads();
#pragma unroll
        for (int k = 0; k < 16; k++) {
            float4 pa0 = *(const float4*)(&sA[k][ty*8]);
            float4 pa1 = *(const float4*)(&sA[k][ty*8+4]);
            float4 pb0 = *(const float4*)(&sB[k][tx*8]);
            float4 pb1 = *(const float4*)(&sB[k][tx*8+4]);
            float av[8] = {pa0.x,pa0.y,pa0.z,pa0.w,pa1.x,pa1.y,pa1.z,pa1.w};
            float bv[8] = {pb0.x,pb0.y,pb0.z,pb0.w,pb1.x,pb1.y,pb1.z,pb1.w};
#pragma unroll
            for (int i = 0; i < 8; i++)
#pragma unroll
                for (int j = 0; j < 8; j++)
                    acc[i][j] += av[i] * bv[j];
        }
    }

    const float NEG = -1e30f;
    float lm[8];
#pragma unroll
    for (int i = 0; i < 8; i++) {
        lm[i] = NEG;
#pragma unroll
        for (int j = 0; j < 8; j++) {
            int n = bn + tx*8 + j;
            if (n < VOC) {
                float l = acc[i][j] + ob[n];
                acc[i][j] = l;
                lm[i] = fmaxf(lm[i], l);
            } else {
                acc[i][j] = NEG;
            }
        }
    }
    __syncthreads();
#pragma unroll
    for (int i = 0; i < 8; i++) red[ty*8 + i][tx] = lm[i];
    __syncthreads();
    if (tid < 128) {
        float m = red[tid][0];
#pragma unroll
        for (int x = 1; x < 16; x++) m = fmaxf(m, red[tid][x]);
        red[tid][16] = m;
    }
    __syncthreads();
    float ls[8];
#pragma unroll
    for (int i = 0; i < 8; i++) {
        float rm = red[ty*8 + i][16];
        float s = 0.0f;
#pragma unroll
        for (int j = 0; j < 8; j++) s += expf(acc[i][j] - rm);
        ls[i] = s;
    }
#pragma unroll
    for (int i = 0; i < 8; i++) {
        int m = bm + ty*8 + i;
        int tv = tgt[m];
#pragma unroll
        for (int j = 0; j < 8; j++)
            if (bn + tx*8 + j == tv) g_tgtlog[m] = acc[i][j];
    }
    __syncthreads();
#pragma unroll
    for (int i = 0; i < 8; i++) red[ty*8 + i][tx] = ls[i];
    __syncthreads();
    if (tid < 128) {
        float s = 0.0f;
#pragma unroll
        for (int x = 0; x < 16; x++) s += red[tid][x];
        size_t m = bm + tid;
        g_pm[m*NCB + blockIdx.x] = red[tid][16];
        g_ps[m*NCB + blockIdx.x] = s;
    }
}

// ---------------- final logsumexp combine + deterministic loss ----------------
__global__ void k_reduce()
{
    __shared__ float sred[256];
    int m = blockIdx.x * 256 + threadIdx.x;   // 25*256 = 6400 exactly
    const float* pm = g_pm + (size_t)m * NCB;
    const float* ps = g_ps + (size_t)m * NCB;
    float M = pm[0];
    for (int j = 1; j < NCB; j++) M = fmaxf(M, pm[j]);
    float S = 0.0f;
    for (int j = 0; j < NCB; j++) S += ps[j] * expf(pm[j] - M);
    float contrib = (M + logf(S) - g_tgtlog[m]) * (1.0f / 64.0f);
    sred[threadIdx.x] = contrib;
    __syncthreads();
    for (int off = 128; off > 0; off >>= 1) {
        if (threadIdx.x < off) sred[threadIdx.x] += sred[threadIdx.x + off];
        __syncthreads();
    }
    if (threadIdx.x == 0) g_lossp[blockIdx.x] = sred[0];
}

__global__ void k_final(float* __restrict__ out)
{
    float s = 0.0f;
    for (int i = 0; i < 25; i++) s += g_lossp[i];
    out[0] = s;
}

// ---------------- host launcher ----------------
extern "C" void kernel_launch(void* const* d_in, const int* in_sizes, int n_in,
                              void* d_out, int out_size)
{
    const float* emb     = (const float*)d_in[0];
    const float* enc_Wih = (const float*)d_in[1];
    const float* enc_Whh = (const float*)d_in[2];
    const float* enc_bih = (const float*)d_in[3];
    const float* enc_bhh = (const float*)d_in[4];
    const float* attn_W  = (const float*)d_in[5];
    const float* attn_b  = (const float*)d_in[6];
    const float* comb_W  = (const float*)d_in[7];
    const float* comb_b  = (const float*)d_in[8];
    const float* dec_Wih = (const float*)d_in[9];
    const float* dec_Whh = (const float*)d_in[10];
    const float* dec_bih = (const float*)d_in[11];
    const float* dec_bhh = (const float*)d_in[12];
    const float* out_W   = (const float*)d_in[13];
    const float* out_b   = (const float*)d_in[14];
    const int*   in_tok  = (const int*)d_in[15];
    const int*   tgt     = (const int*)d_in[16];

    float *p_encGx, *p_attnx, *p_combx, *p_enc0, *p_enc0W;
    int *p_dectok;
    cudaGetSymbolAddress((void**)&p_encGx, g_encGx);
    cudaGetSymbolAddress((void**)&p_attnx, g_attnx);
    cudaGetSymbolAddress((void**)&p_combx, g_combx);
    cudaGetSymbolAddress((void**)&p_enc0,  g_enc0);
    cudaGetSymbolAddress((void**)&p_enc0W, g_enc0W);
    cudaGetSymbolAddress((void**)&p_dectok, g_dectok);

    // init
    k_init<<<128, 256>>>(tgt);

    // phase A: all x-dependent GEMMs (batched, token gather fused into A-load)
    k_sgemm128<true><<<dim3(12, 200), 256>>>(emb, in_tok,  enc_Wih, HID,  enc_bih, p_encGx, LEN*BSZ, G3,   HID);
    k_sgemm128<true><<<dim3(4, 50),  256>>>(emb, p_dectok, attn_W,  1024, attn_b,  p_attnx, MROWS,   LMAX, HID);
    k_sgemm128<true><<<dim3(4, 50),  256>>>(emb, p_dectok, comb_W,  1024, comb_b,  p_combx, MROWS,   HID,  HID);

    // phase B1: persistent encoder (1 node)
    k_encoder<<<NBLK, 256>>>(enc_Whh, enc_bhh);

    // enc0W = enc0 @ comb_W[:, H:]^T
    k_sgemm128<false><<<dim3(4, 1), 256>>>(p_enc0, (const int*)nullptr, comb_W + 512, 1024,
                                           (const float*)nullptr, p_enc0W, BSZ, HID, HID);

    // phase B2: persistent decoder (1 node)
    k_decoder<<<NBLK, 256>>>(attn_W, dec_Wih, dec_Whh, dec_bih, dec_bhh);

    // phase C: one batched 6400x50000x512 projection with fused logsumexp partials
    k_outgemm<<<dim3(NCB, 50), 256>>>(out_W, out_b, tgt);
    k_reduce<<<25, 256>>>();
    k_final<<<1, 1>>>((float*)d_out);
}

// round 6
// speedup vs baseline: 1.3698x; 1.3698x over previous
#include <cuda_runtime.h>
#include <cuda_bf16.h>
#include <mma.h>
#include <math.h>

using namespace nvcuda;

// ---------------- problem constants ----------------
#define BSZ   64
#define HID   512
#define G3    1536          // 3*HID
#define LEN   400           // encoder length
#define TOUT  100           // decoder steps
#define VOC   50000
#define LMAX  400
#define MROWS (TOUT*BSZ)    // 6400 decoder rows
#define NCB   782           // phase-C column blocks: ceil(50000/64)
#define NBLK  148           // persistent grid size (<= SM count, all co-resident)
#define KDIM  512

// ---------------- device scratch (static, allocation-free) ----------------
__device__ float g_encGx[(size_t)LEN*BSZ*G3];    // x-gates for encoder (raw, no bias)
__device__ float g_attnx[(size_t)TOUT*BSZ*LMAX]; // x-part of attn logits, incl attn_b
__device__ float g_combx[(size_t)TOUT*BSZ*HID];  // x-part of combine, incl comb_b
__device__ int   g_dectok[TOUT*BSZ];
__device__ float g_h[BSZ*HID];                   // current hidden
__device__ float g_enc0[BSZ*HID];                // encoder output at t=0
__device__ float g_enc0W[BSZ*HID];               // enc0 @ comb_W[:,H:]^T
__device__ float g_part[4*BSZ*G3];               // K-split partials for step GEMMs
__device__ float g_a0[BSZ];
__device__ float g_c[BSZ*HID];
__device__ __nv_bfloat16 g_H2bf[(size_t)MROWS*HID];   // all decoder hiddens (bf16)
__device__ __nv_bfloat16 g_embbf[(size_t)VOC*HID];    // emb in bf16
__device__ __nv_bfloat16 g_Wobf[(size_t)VOC*HID];     // out_W in bf16
__device__ __nv_bfloat16 g_Wihbf[(size_t)G3*HID];     // enc_Wih in bf16
__device__ float g_pm[(size_t)MROWS*NCB];        // per-tile row max
__device__ float g_ps[(size_t)MROWS*NCB];        // per-tile row sumexp
__device__ float g_tgtlog[MROWS];                // logits at target index
__device__ float g_lossp[32];                    // per-block loss partials

// grid barrier state
__device__ unsigned g_barcnt;
__device__ unsigned g_bargen;

__device__ __forceinline__ float sigmf(float x) { return 1.0f / (1.0f + expf(-x)); }

__device__ __forceinline__ void gridbar(unsigned &gen)
{
    __syncthreads();
    if (threadIdx.x == 0) {
        __threadfence();
        unsigned prev = atomicAdd(&g_barcnt, 1u);
        if (prev == NBLK - 1u) {
            atomicExch(&g_barcnt, 0u);
            __threadfence();
            atomicAdd(&g_bargen, 1u);
        } else {
            while (atomicAdd(&g_bargen, 0u) == gen) __nanosleep(64);
        }
        gen++;
    }
    __syncthreads();
}

// ---------------- fp32 -> bf16 conversion ----------------
__global__ void k_tobf(const float* __restrict__ s, __nv_bfloat16* __restrict__ d, int n)
{
    int i = (blockIdx.x * 256 + threadIdx.x) << 2;
    if (i < n) {
        float4 v = *(const float4*)(s + i);
        *(__nv_bfloat162*)(d + i)     = __floats2bfloat162_rn(v.x, v.y);
        *(__nv_bfloat162*)(d + i + 2) = __floats2bfloat162_rn(v.z, v.w);
    }
}

// ---------------- init: zero h, build decoder tokens ----------------
__global__ void k_init(const int* __restrict__ tgt)
{
    int i = blockIdx.x * 256 + threadIdx.x;
    if (i < BSZ*HID) g_h[i] = 0.0f;
    if (i < TOUT*BSZ) {
        int t = i / BSZ, b = i % BSZ;
        g_dectok[i] = (t == 0) ? 1 : tgt[(t-1)*BSZ + b];
    }
}

// ================= bf16 WMMA GEMM, 128(M) x 64(N) block, K=512 =================
// MODE 0: A row m = Abf[gidx[m]] (token gather), store raw C to Cout (no bias).
// MODE 1: A row m = Abf[m], fused bias + streaming logsumexp epilogue
//         (g_pm/g_ps partials + target logit); nothing stored to Cout.
template<int MODE>
__global__ void __launch_bounds__(256)
k_wgemm(const __nv_bfloat16* __restrict__ Abf,
        const int* __restrict__ gidx,
        const __nv_bfloat16* __restrict__ Bbf,
        const float* __restrict__ bias,
        float* __restrict__ Cout, int ldC,
        const int* __restrict__ tgt,
        int Ncols)
{
    // shared buffer, reused: input tiles during K-loop, C tile during epilogue
    __shared__ __align__(16) char sbuf[128*72*4];
    __nv_bfloat16* sA = (__nv_bfloat16*)sbuf;             // 128 x 40 bf16
    __nv_bfloat16* sB = (__nv_bfloat16*)(sbuf + 10240);   // 64 x 40 bf16
    float* sC = (float*)sbuf;                             // 128 x 72 f32 (epilogue)

    const int tid  = threadIdx.x;
    const int warp = tid >> 5;
    const int wm = warp >> 1;        // 0..3
    const int wn = warp & 1;         // 0..1
    const int bm = blockIdx.y * 128;
    const int bn = blockIdx.x * 64;

    const int cr = tid >> 2;         // 0..63
    const int ck = (tid & 3) << 3;   // 0,8,16,24

    size_t aoff0, aoff1;
    if (MODE == 0) {
        aoff0 = (size_t)gidx[bm + cr]      * KDIM + ck;
        aoff1 = (size_t)gidx[bm + cr + 64] * KDIM + ck;
    } else {
        aoff0 = (size_t)(bm + cr)      * KDIM + ck;
        aoff1 = (size_t)(bm + cr + 64) * KDIM + ck;
    }
    int nbr = bn + cr;
    if (nbr >= Ncols) nbr = Ncols - 1;
    size_t boff = (size_t)nbr * KDIM + ck;

    const int sa0 = cr*40 + ck;
    const int sa1 = (cr + 64)*40 + ck;

    uint4 ra0 = *(const uint4*)(Abf + aoff0);
    uint4 ra1 = *(const uint4*)(Abf + aoff1);
    uint4 rb  = *(const uint4*)(Bbf + boff);

    wmma::fragment<wmma::accumulator, 16, 16, 16, float> fc[2][2];
    for (int mi = 0; mi < 2; mi++)
        for (int ni = 0; ni < 2; ni++)
            wmma::fill_fragment(fc[mi][ni], 0.0f);

    for (int it = 0; it < 16; it++) {
        __syncthreads();
        *(uint4*)(sA + sa0) = ra0;
        *(uint4*)(sA + sa1) = ra1;
        *(uint4*)(sB + sa0) = rb;
        __syncthreads();
        if (it < 15) {
            int kg = (it + 1) * 32;
            ra0 = *(const uint4*)(Abf + aoff0 + kg);
            ra1 = *(const uint4*)(Abf + aoff1 + kg);
            rb  = *(const uint4*)(Bbf + boff + kg);
        }
        for (int kk = 0; kk < 32; kk += 16) {
            wmma::fragment<wmma::matrix_a, 16, 16, 16, __nv_bfloat16, wmma::row_major> fa[2];
            wmma::fragment<wmma::matrix_b, 16, 16, 16, __nv_bfloat16, wmma::col_major> fb[2];
            wmma::load_matrix_sync(fa[0], sA + (wm*32     )*40 + kk, 40);
            wmma::load_matrix_sync(fa[1], sA + (wm*32 + 16)*40 + kk, 40);
            wmma::load_matrix_sync(fb[0], sB + (wn*32     )*40 + kk, 40);
            wmma::load_matrix_sync(fb[1], sB + (wn*32 + 16)*40 + kk, 40);
            for (int mi = 0; mi < 2; mi++)
                for (int ni = 0; ni < 2; ni++)
                    wmma::mma_sync(fc[mi][ni], fa[mi], fb[ni], fc[mi][ni]);
        }
    }

    if (MODE == 0) {
        for (int mi = 0; mi < 2; mi++)
            for (int ni = 0; ni < 2; ni++) {
                size_t row = bm + wm*32 + mi*16;
                int col = bn + wn*32 + ni*16;
                wmma::store_matrix_sync(Cout + row * (size_t)ldC + col,
                                        fc[mi][ni], ldC, wmma::mem_row_major);
            }
    } else {
        __syncthreads();
        for (int mi = 0; mi < 2; mi++)
            for (int ni = 0; ni < 2; ni++)
                wmma::store_matrix_sync(sC + (wm*32 + mi*16)*72 + wn*32 + ni*16,
                                        fc[mi][ni], 72, wmma::mem_row_major);
        __syncthreads();

        // 2 threads per row: thread pair (2r, 2r+1) handles halves of 64 cols
        int r  = tid >> 1;
        int hf = tid & 1;
        float* crow = sC + r*72 + hf*32;
        float mx = -1e30f;
        for (int c = 0; c < 32; c++) {
            int gc = bn + hf*32 + c;
            float v = (gc < Ncols) ? (crow[c] + bias[gc]) : -1e30f;
            crow[c] = v;
            mx = fmaxf(mx, v);
        }
        float s = 0.0f;
        for (int c = 0; c < 32; c++) s += expf(crow[c] - mx);

        float mo = __shfl_xor_sync(0xffffffffu, mx, 1);
        float so = __shfl_xor_sync(0xffffffffu, s,  1);
        float M = fmaxf(mx, mo);
        float S = s * expf(mx - M) + so * expf(mo - M);

        int rg = bm + r;
        int tv = tgt[rg];
        int lc = tv - bn - hf*32;
        if (lc >= 0 && lc < 32) g_tgtlog[rg] = crow[lc];
        if (hf == 0) {
            g_pm[(size_t)rg * NCB + blockIdx.x] = M;
            g_ps[(size_t)rg * NCB + blockIdx.x] = S;
        }
    }
}

// ---------------- generic fp32 SGEMM (small phase-A ops) ----------------
template<bool GATHER>
__global__ void __launch_bounds__(256)
k_sgemm128(const float* __restrict__ A,
           const int*  __restrict__ gidx,
           const float* __restrict__ Bw, int ldb,
           const float* __restrict__ bias,
           float* __restrict__ C,
           int M, int N, int K)
{
    __shared__ __align__(16) float sA[16][128];
    __shared__ __align__(16) float sB[16][128];
    const int tid = threadIdx.x;
    const int bm = blockIdx.y * 128;
    const int bn = blockIdx.x * 128;
    const int tx = tid & 15;
    const int ty = tid >> 4;
    const int lr = tid >> 2;
    const int lk = (tid & 3) << 2;

    int m0 = bm + lr, m1 = m0 + 64;
    const bool mv0 = m0 < M, mv1 = m1 < M;
    size_t ar0, ar1;
    if (GATHER) {
        ar0 = (size_t)(mv0 ? gidx[m0] : gidx[0]) * (size_t)K;
        ar1 = (size_t)(mv1 ? gidx[m1] : gidx[0]) * (size_t)K;
    } else {
        ar0 = (size_t)(mv0 ? m0 : 0) * (size_t)K;
        ar1 = (size_t)(mv1 ? m1 : 0) * (size_t)K;
    }
    int n0 = bn + lr, n1 = n0 + 64;
    size_t br0 = (size_t)(n0 < N ? n0 : 0) * (size_t)ldb;
    size_t br1 = (size_t)(n1 < N ? n1 : 0) * (size_t)ldb;

    float acc[8][8];
#pragma unroll
    for (int i = 0; i < 8; i++)
#pragma unroll
        for (int j = 0; j < 8; j++) acc[i][j] = 0.0f;

    for (int kb = 0; kb < K; kb += 16) {
        float4 a0 = *(const float4*)(A  + ar0 + kb + lk);
        float4 a1 = *(const float4*)(A  + ar1 + kb + lk);
        float4 b0 = *(const float4*)(Bw + br0 + kb + lk);
        float4 b1 = *(const float4*)(Bw + br1 + kb + lk);
        __syncthreads();
        sA[lk+0][lr] = a0.x; sA[lk+1][lr] = a0.y; sA[lk+2][lr] = a0.z; sA[lk+3][lr] = a0.w;
        sA[lk+0][lr+64] = a1.x; sA[lk+1][lr+64] = a1.y; sA[lk+2][lr+64] = a1.z; sA[lk+3][lr+64] = a1.w;
        sB[lk+0][lr] = b0.x; sB[lk+1][lr] = b0.y; sB[lk+2][lr] = b0.z; sB[lk+3][lr] = b0.w;
        sB[lk+0][lr+64] = b1.x; sB[lk+1][lr+64] = b1.y; sB[lk+2][lr+64] = b1.z; sB[lk+3][lr+64] = b1.w;
        __syncthreads();
#pragma unroll
        for (int k = 0; k < 16; k++) {
            float4 pa0 = *(const float4*)(&sA[k][ty*8]);
            float4 pa1 = *(const float4*)(&sA[k][ty*8+4]);
            float4 pb0 = *(const float4*)(&sB[k][tx*8]);
            float4 pb1 = *(const float4*)(&sB[k][tx*8+4]);
            float av[8] = {pa0.x, pa0.y, pa0.z, pa0.w, pa1.x, pa1.y, pa1.z, pa1.w};
            float bv[8] = {pb0.x, pb0.y, pb0.z, pb0.w, pb1.x, pb1.y, pb1.z, pb1.w};
#pragma unroll
            for (int i = 0; i < 8; i++)
#pragma unroll
                for (int j = 0; j < 8; j++)
                    acc[i][j] += av[i] * bv[j];
        }
    }

#pragma unroll
    for (int i = 0; i < 8; i++) {
        int m = bm + ty*8 + i;
        if (m < M) {
            float* crow = C + (size_t)m * (size_t)N;
#pragma unroll
            for (int j = 0; j < 8; j++) {
                int n = bn + tx*8 + j;
                if (n < N) crow[n] = acc[i][j] + (bias ? bias[n] : 0.0f);
            }
        }
    }
}

// ---------------- per-task 64x64 step-GEMM helper ----------------
__device__ __forceinline__ void step_gemm_task(
    const float* __restrict__ A, const float* __restrict__ Bm,
    int nb, int kbase, int Kloc, float* __restrict__ Cp, float* sm)
{
    float* sA = sm;
    float* sB = sm + 1024;
    const int tid = threadIdx.x;
    const int tx = tid & 15, ty = tid >> 4;
    const int lr = tid >> 2, lk = (tid & 3) << 2;
    const int bn = nb * 64;

    float acc[4][4];
#pragma unroll
    for (int i = 0; i < 4; i++)
#pragma unroll
        for (int j = 0; j < 4; j++) acc[i][j] = 0.0f;

    for (int kb = 0; kb < Kloc; kb += 16) {
        int kg = kbase + kb;
        float4 av = *(const float4*)(A  + lr*HID + kg + lk);
        float4 bv = *(const float4*)(Bm + (size_t)(bn + lr)*HID + kg + lk);
        __syncthreads();
        sA[(lk+0)*64+lr] = av.x; sA[(lk+1)*64+lr] = av.y; sA[(lk+2)*64+lr] = av.z; sA[(lk+3)*64+lr] = av.w;
        sB[(lk+0)*64+lr] = bv.x; sB[(lk+1)*64+lr] = bv.y; sB[(lk+2)*64+lr] = bv.z; sB[(lk+3)*64+lr] = bv.w;
        __syncthreads();
#pragma unroll
        for (int k = 0; k < 16; k++) {
            float4 pa = *(const float4*)(sA + k*64 + ty*4);
            float4 pb = *(const float4*)(sB + k*64 + tx*4);
            float a4[4] = {pa.x, pa.y, pa.z, pa.w};
            float b4[4] = {pb.x, pb.y, pb.z, pb.w};
#pragma unroll
            for (int i = 0; i < 4; i++)
#pragma unroll
                for (int j = 0; j < 4; j++)
                    acc[i][j] += a4[i] * b4[j];
        }
    }
    __syncthreads();
#pragma unroll
    for (int i = 0; i < 4; i++)
#pragma unroll
        for (int j = 0; j < 4; j++)
            Cp[(ty*4 + i)*G3 + bn + tx*4 + j] = acc[i][j];
}

// ---------------- persistent encoder ----------------
__global__ void __launch_bounds__(256)
k_encoder(const float* __restrict__ Whh,
          const float* __restrict__ bih, const float* __restrict__ bhh)
{
    __shared__ __align__(16) float sm[2048];
    unsigned gen = 0;
    if (threadIdx.x == 0) gen = atomicAdd(&g_bargen, 0u);
    const int blk = blockIdx.x;

    for (int t = 0; t < LEN; t++) {
        if (blk < 96) {
            int ks = blk / 24, nb = blk % 24;
            step_gemm_task(g_h, Whh, nb, ks*128, 128, g_part + (size_t)ks*BSZ*G3, sm);
        }
        gridbar(gen);
        if (blk < 128) {
            int idx = blk*256 + threadIdx.x;
            int b = idx >> 9, j = idx & 511;
            int base = b * G3;
            float hr = bhh[j], hz = bhh[j+512], hn = bhh[j+1024];
#pragma unroll
            for (int s = 0; s < 4; s++) {
                const float* p = g_part + (size_t)s * BSZ * G3 + base;
                hr += p[j]; hz += p[j+512]; hn += p[j+1024];
            }
            const float* gx = g_encGx + ((size_t)t*BSZ + b) * G3;
            float r = sigmf(gx[j] + bih[j] + hr);
            float z = sigmf(gx[j+512] + bih[j+512] + hz);
            float n = tanhf(gx[j+1024] + bih[j+1024] + r * hn);
            float hp = g_h[idx];
            float h2 = (1.0f - z) * n + z * hp;
            g_h[idx] = h2;
            if (t == 0) g_enc0[idx] = h2;
        }
        gridbar(gen);
    }
}

// ---------------- persistent decoder ----------------
__global__ void __launch_bounds__(256)
k_decoder(const float* __restrict__ attn_W,
          const float* __restrict__ dec_Wih, const float* __restrict__ dec_Whh,
          const float* __restrict__ bih, const float* __restrict__ bhh)
{
    __shared__ __align__(16) float sm[2048];
    unsigned gen = 0;
    if (threadIdx.x == 0) gen = atomicAdd(&g_bargen, 0u);
    const int blk = blockIdx.x;
    const int tid = threadIdx.x;

    for (int t = 0; t < TOUT; t++) {
        if (blk < 64) {
            const int b = blk;
            float* sh = sm;
            float* slg = sm + 512;
            float* sred = sm + 912;
            sh[tid]       = g_h[b*HID + tid];
            sh[tid + 256] = g_h[b*HID + tid + 256];
            __syncthreads();
            const float4* h4 = (const float4*)sh;
            for (int l = tid; l < LMAX; l += 256) {
                const float4* w4 = (const float4*)(attn_W + (size_t)l*1024 + 512);
                float s = 0.0f;
#pragma unroll 4
                for (int k = 0; k < 128; k++) {
                    float4 w = w4[k], h = h4[k];
                    s += w.x*h.x + w.y*h.y + w.z*h.z + w.w*h.w;
                }
                slg[l] = g_attnx[((size_t)t*BSZ + b)*LMAX + l] + s;
            }
            __syncthreads();
            float lm = -1e30f;
            for (int l = tid; l < LMAX; l += 256) lm = fmaxf(lm, slg[l]);
            sred[tid] = lm; __syncthreads();
            for (int off = 128; off > 0; off >>= 1) {
                if (tid < off) sred[tid] = fmaxf(sred[tid], sred[tid+off]);
                __syncthreads();
            }
            float mx = sred[0];
            __syncthreads();
            float ls = 0.0f;
            for (int l = tid; l < LMAX; l += 256) ls += expf(slg[l] - mx);
            sred[tid] = ls; __syncthreads();
            for (int off = 128; off > 0; off >>= 1) {
                if (tid < off) sred[tid] += sred[tid+off];
                __syncthreads();
            }
            if (tid == 0) g_a0[b] = expf(slg[0] - mx) / sred[0];
        }
        gridbar(gen);
        if (blk < 128) {
            int idx = blk*256 + tid;
            int b = idx >> 9, j = idx & 511;
            float v = g_combx[((size_t)t*BSZ + b)*HID + j] + g_a0[b] * g_enc0W[idx];
            g_c[idx] = v > 0.0f ? v : 0.0f;
        }
        gridbar(gen);
        if (blk < 96) {
            int group = blk / 48, rem = blk % 48;
            int nb = rem % 24, ks = rem / 24;
            const float* A  = group ? g_h : g_c;
            const float* Bm = group ? dec_Whh : dec_Wih;
            step_gemm_task(A, Bm, nb, ks*256, 256,
                           g_part + (size_t)(group*2 + ks)*BSZ*G3, sm);
        }
        gridbar(gen);
        if (blk < 128) {
            int idx = blk*256 + tid;
            int b = idx >> 9, j = idx & 511;
            int base = b * G3;
            float ir = bih[j], iz = bih[j+512], in = bih[j+1024];
            float hr = bhh[j], hz = bhh[j+512], hn = bhh[j+1024];
#pragma unroll
            for (int s = 0; s < 2; s++) {
                const float* pi = g_part + (size_t)s * BSZ * G3 + base;
                const float* ph = g_part + (size_t)(s+2) * BSZ * G3 + base;
                ir += pi[j]; iz += pi[j+512]; in += pi[j+1024];
                hr += ph[j]; hz += ph[j+512]; hn += ph[j+1024];
            }
            float r = sigmf(ir + hr);
            float z = sigmf(iz + hz);
            float n = tanhf(in + r * hn);
            float hp = g_h[idx];
            float h2 = (1.0f - z) * n + z * hp;
            g_h[idx] = h2;
            g_H2bf[(size_t)t*BSZ*HID + idx] = __float2bfloat16(h2);
        }
        gridbar(gen);
    }
}

// ---------------- final logsumexp combine + deterministic loss ----------------
__global__ void k_reduce()
{
    __shared__ float sred[256];
    int m = blockIdx.x * 256 + threadIdx.x;   // 25*256 = 6400 exactly
    const float* pm = g_pm + (size_t)m * NCB;
    const float* ps = g_ps + (size_t)m * NCB;
    float M = pm[0];
    for (int j = 1; j < NCB; j++) M = fmaxf(M, pm[j]);
    float S = 0.0f;
    for (int j = 0; j < NCB; j++) S += ps[j] * expf(pm[j] - M);
    float contrib = (M + logf(S) - g_tgtlog[m]) * (1.0f / 64.0f);
    sred[threadIdx.x] = contrib;
    __syncthreads();
    for (int off = 128; off > 0; off >>= 1) {
        if (threadIdx.x < off) sred[threadIdx.x] += sred[threadIdx.x + off];
        __syncthreads();
    }
    if (threadIdx.x == 0) g_lossp[blockIdx.x] = sred[0];
}

__global__ void k_final(float* __restrict__ out)
{
    float s = 0.0f;
    for (int i = 0; i < 25; i++) s += g_lossp[i];
    out[0] = s;
}

// ---------------- host launcher ----------------
extern "C" void kernel_launch(void* const* d_in, const int* in_sizes, int n_in,
                              void* d_out, int out_size)
{
    const float* emb     = (const float*)d_in[0];
    const float* enc_Wih = (const float*)d_in[1];
    const float* enc_Whh = (const float*)d_in[2];
    const float* enc_bih = (const float*)d_in[3];
    const float* enc_bhh = (const float*)d_in[4];
    const float* attn_W  = (const float*)d_in[5];
    const float* attn_b  = (const float*)d_in[6];
    const float* comb_W  = (const float*)d_in[7];
    const float* comb_b  = (const float*)d_in[8];
    const float* dec_Wih = (const float*)d_in[9];
    const float* dec_Whh = (const float*)d_in[10];
    const float* dec_bih = (const float*)d_in[11];
    const float* dec_bhh = (const float*)d_in[12];
    const float* out_W   = (const float*)d_in[13];
    const float* out_b   = (const float*)d_in[14];
    const int*   in_tok  = (const int*)d_in[15];
    const int*   tgt     = (const int*)d_in[16];

    float *p_attnx, *p_combx, *p_enc0, *p_enc0W, *p_encGx;
    int *p_dectok;
    __nv_bfloat16 *p_embbf, *p_Wobf, *p_Wihbf, *p_H2bf;
    cudaGetSymbolAddress((void**)&p_encGx, g_encGx);
    cudaGetSymbolAddress((void**)&p_attnx, g_attnx);
    cudaGetSymbolAddress((void**)&p_combx, g_combx);
    cudaGetSymbolAddress((void**)&p_enc0,  g_enc0);
    cudaGetSymbolAddress((void**)&p_enc0W, g_enc0W);
    cudaGetSymbolAddress((void**)&p_dectok, g_dectok);
    cudaGetSymbolAddress((void**)&p_embbf, g_embbf);
    cudaGetSymbolAddress((void**)&p_Wobf,  g_Wobf);
    cudaGetSymbolAddress((void**)&p_Wihbf, g_Wihbf);
    cudaGetSymbolAddress((void**)&p_H2bf,  g_H2bf);

    // init + bf16 conversions
    k_init<<<128, 256>>>(tgt);
    k_tobf<<<(VOC*HID)/1024, 256>>>(emb,     p_embbf, VOC*HID);
    k_tobf<<<(VOC*HID)/1024, 256>>>(out_W,   p_Wobf,  VOC*HID);
    k_tobf<<<(G3*HID)/1024,  256>>>(enc_Wih, p_Wihbf, G3*HID);

    // phase A: encGx via WMMA bf16 (token gather fused; bias added in encoder fuse)
    k_wgemm<0><<<dim3(24, 200), 256>>>(p_embbf, in_tok, p_Wihbf,
                                       (const float*)0, p_encGx, G3,
                                       (const int*)0, G3);
    // small fp32 GEMMs for decoder x-parts
    k_sgemm128<true><<<dim3(4, 50), 256>>>(emb, p_dectok, attn_W, 1024, attn_b, p_attnx, MROWS, LMAX, HID);
    k_sgemm128<true><<<dim3(4, 50), 256>>>(emb, p_dectok, comb_W, 1024, comb_b, p_combx, MROWS, HID,  HID);

    // phase B1: persistent encoder
    k_encoder<<<NBLK, 256>>>(enc_Whh, enc_bih, enc_bhh);

    // enc0W = enc0 @ comb_W[:, H:]^T
    k_sgemm128<false><<<dim3(4, 1), 256>>>(p_enc0, (const int*)0, comb_W + 512, 1024,
                                           (const float*)0, p_enc0W, BSZ, HID, HID);

    // phase B2: persistent decoder
    k_decoder<<<NBLK, 256>>>(attn_W, dec_Wih, dec_Whh, dec_bih, dec_bhh);

    // phase C: WMMA bf16 projection with fused logsumexp partials
    k_wgemm<1><<<dim3(NCB, 50), 256>>>(p_H2bf, (const int*)0, p_Wobf, out_b,
                                       (float*)0, 0, tgt, VOC);
    k_reduce<<<25, 256>>>();
    k_final<<<1, 1>>>((float*)d_out);
}

// round 7
// speedup vs baseline: 1.6621x; 1.2134x over previous
#include <cuda_runtime.h>
#include <cuda_bf16.h>
#include <mma.h>
#include <math.h>

using namespace nvcuda;

// ---------------- problem constants ----------------
#define BSZ   64
#define HID   512
#define G3    1536          // 3*HID
#define LEN   400           // encoder length
#define TOUT  100           // decoder steps
#define VOC   50000
#define LMAX  400
#define MROWS (TOUT*BSZ)    // 6400 decoder rows
#define NCB   782           // phase-C column blocks: ceil(50000/64)
#define NBLK  148           // persistent grid size (<= SM count, all co-resident)
#define KDIM  512

// ---------------- device scratch (static, allocation-free) ----------------
__device__ float g_encGx[(size_t)LEN*BSZ*G3];    // x-gates for encoder (raw, no bias)
__device__ float g_attnx[(size_t)TOUT*BSZ*LMAX]; // x-part of attn logits, incl attn_b
__device__ float g_combx[(size_t)TOUT*BSZ*HID];  // x-part of combine, incl comb_b
__device__ int   g_dectok[TOUT*BSZ];
__device__ float g_h[BSZ*HID];                   // current hidden (fp32)
__device__ __nv_bfloat16 g_hbf[BSZ*HID];         // current hidden (bf16, GEMM input)
__device__ __nv_bfloat16 g_cbf[BSZ*HID];         // combined input (bf16, GEMM input)
__device__ float g_enc0[BSZ*HID];                // encoder output at t=0
__device__ float g_enc0W[BSZ*HID];               // enc0 @ comb_W[:,H:]^T
__device__ float g_part[4*BSZ*G3];               // K-split partials for step GEMMs
__device__ float g_a0[BSZ];
__device__ __nv_bfloat16 g_H2bf[(size_t)MROWS*HID];   // all decoder hiddens (bf16)
__device__ __nv_bfloat16 g_embbf[(size_t)VOC*HID];    // emb in bf16
__device__ __nv_bfloat16 g_Wobf[(size_t)VOC*HID];     // out_W in bf16
__device__ __nv_bfloat16 g_Wihbf[(size_t)G3*HID];     // enc_Wih in bf16
__device__ __nv_bfloat16 g_Whhbf[(size_t)G3*HID];     // enc_Whh in bf16
__device__ __nv_bfloat16 g_dWihbf[(size_t)G3*HID];    // dec_Wih in bf16
__device__ __nv_bfloat16 g_dWhhbf[(size_t)G3*HID];    // dec_Whh in bf16
__device__ float g_pm[(size_t)MROWS*NCB];        // per-tile row max
__device__ float g_ps[(size_t)MROWS*NCB];        // per-tile row sumexp
__device__ float g_tgtlog[MROWS];                // logits at target index
__device__ float g_lossp[32];                    // per-block loss partials

// grid barrier state
__device__ unsigned g_barcnt;
__device__ unsigned g_bargen;

__device__ __forceinline__ float sigmf(float x) { return 1.0f / (1.0f + expf(-x)); }

__device__ __forceinline__ void gridbar(unsigned &gen)
{
    __syncthreads();
    if (threadIdx.x == 0) {
        __threadfence();
        unsigned prev = atomicAdd(&g_barcnt, 1u);
        if (prev == NBLK - 1u) {
            atomicExch(&g_barcnt, 0u);
            __threadfence();
            atomicAdd(&g_bargen, 1u);
        } else {
            while (atomicAdd(&g_bargen, 0u) == gen) __nanosleep(64);
        }
        gen++;
    }
    __syncthreads();
}

// ---------------- fp32 -> bf16 conversion ----------------
__global__ void k_tobf(const float* __restrict__ s, __nv_bfloat16* __restrict__ d, int n)
{
    int i = (blockIdx.x * 256 + threadIdx.x) << 2;
    if (i < n) {
        float4 v = *(const float4*)(s + i);
        *(__nv_bfloat162*)(d + i)     = __floats2bfloat162_rn(v.x, v.y);
        *(__nv_bfloat162*)(d + i + 2) = __floats2bfloat162_rn(v.z, v.w);
    }
}

// ---------------- init: zero h, build decoder tokens ----------------
__global__ void k_init(const int* __restrict__ tgt)
{
    int i = blockIdx.x * 256 + threadIdx.x;
    if (i < BSZ*HID) {
        g_h[i] = 0.0f;
        g_hbf[i] = __float2bfloat16(0.0f);
    }
    if (i < TOUT*BSZ) {
        int t = i / BSZ, b = i % BSZ;
        g_dectok[i] = (t == 0) ? 1 : tgt[(t-1)*BSZ + b];
    }
}

// ================= bf16 WMMA GEMM, 128(M) x 64(N) block, K=512, double-buffered =================
// MODE 0: A row m = Abf[gidx[m]] (token gather), store raw C to Cout (no bias).
// MODE 1: A row m = Abf[m], fused bias + streaming logsumexp epilogue.
template<int MODE>
__global__ void __launch_bounds__(256)
k_wgemm(const __nv_bfloat16* __restrict__ Abf,
        const int* __restrict__ gidx,
        const __nv_bfloat16* __restrict__ Bbf,
        const float* __restrict__ bias,
        float* __restrict__ Cout, int ldC,
        const int* __restrict__ tgt,
        int Ncols)
{
    // shared buffer: two double-buffered input tiles (2 x 15360B), reused as C tile (36864B)
    __shared__ __align__(16) char sbuf[128*72*4];
    float* sC = (float*)sbuf;

    const int tid  = threadIdx.x;
    const int warp = tid >> 5;
    const int wm = warp >> 1;        // 0..3
    const int wn = warp & 1;         // 0..1
    const int bm = blockIdx.y * 128;
    const int bn = blockIdx.x * 64;

    const int cr = tid >> 2;         // 0..63
    const int ck = (tid & 3) << 3;   // 0,8,16,24

    size_t aoff0, aoff1;
    if (MODE == 0) {
        aoff0 = (size_t)gidx[bm + cr]      * KDIM + ck;
        aoff1 = (size_t)gidx[bm + cr + 64] * KDIM + ck;
    } else {
        aoff0 = (size_t)(bm + cr)      * KDIM + ck;
        aoff1 = (size_t)(bm + cr + 64) * KDIM + ck;
    }
    int nbr = bn + cr;
    if (nbr >= Ncols) nbr = Ncols - 1;
    size_t boff = (size_t)nbr * KDIM + ck;

    const int sa0 = cr*40 + ck;
    const int sa1 = (cr + 64)*40 + ck;

    __nv_bfloat16* sAb0 = (__nv_bfloat16*)sbuf;
    __nv_bfloat16* sBb0 = (__nv_bfloat16*)(sbuf + 10240);
    __nv_bfloat16* sAb1 = (__nv_bfloat16*)(sbuf + 15360);
    __nv_bfloat16* sBb1 = (__nv_bfloat16*)(sbuf + 25600);

    uint4 ra0 = *(const uint4*)(Abf + aoff0);
    uint4 ra1 = *(const uint4*)(Abf + aoff1);
    uint4 rb  = *(const uint4*)(Bbf + boff);
    *(uint4*)(sAb0 + sa0) = ra0;
    *(uint4*)(sAb0 + sa1) = ra1;
    *(uint4*)(sBb0 + sa0) = rb;
    __syncthreads();

    wmma::fragment<wmma::accumulator, 16, 16, 16, float> fc[2][2];
    for (int mi = 0; mi < 2; mi++)
        for (int ni = 0; ni < 2; ni++)
            wmma::fill_fragment(fc[mi][ni], 0.0f);

    for (int it = 0; it < 16; it++) {
        if (it < 15) {
            int kg = (it + 1) * 32;
            ra0 = *(const uint4*)(Abf + aoff0 + kg);
            ra1 = *(const uint4*)(Abf + aoff1 + kg);
            rb  = *(const uint4*)(Bbf + boff + kg);
        }
        __nv_bfloat16* cA = (it & 1) ? sAb1 : sAb0;
        __nv_bfloat16* cB = (it & 1) ? sBb1 : sBb0;
        for (int kk = 0; kk < 32; kk += 16) {
            wmma::fragment<wmma::matrix_a, 16, 16, 16, __nv_bfloat16, wmma::row_major> fa[2];
            wmma::fragment<wmma::matrix_b, 16, 16, 16, __nv_bfloat16, wmma::col_major> fb[2];
            wmma::load_matrix_sync(fa[0], cA + (wm*32     )*40 + kk, 40);
            wmma::load_matrix_sync(fa[1], cA + (wm*32 + 16)*40 + kk, 40);
            wmma::load_matrix_sync(fb[0], cB + (wn*32     )*40 + kk, 40);
            wmma::load_matrix_sync(fb[1], cB + (wn*32 + 16)*40 + kk, 40);
            for (int mi = 0; mi < 2; mi++)
                for (int ni = 0; ni < 2; ni++)
                    wmma::mma_sync(fc[mi][ni], fa[mi], fb[ni], fc[mi][ni]);
        }
        if (it < 15) {
            __nv_bfloat16* nA = (it & 1) ? sAb0 : sAb1;
            __nv_bfloat16* nB = (it & 1) ? sBb0 : sBb1;
            *(uint4*)(nA + sa0) = ra0;
            *(uint4*)(nA + sa1) = ra1;
            *(uint4*)(nB + sa0) = rb;
        }
        __syncthreads();
    }

    if (MODE == 0) {
        for (int mi = 0; mi < 2; mi++)
            for (int ni = 0; ni < 2; ni++) {
                size_t row = bm + wm*32 + mi*16;
                int col = bn + wn*32 + ni*16;
                wmma::store_matrix_sync(Cout + row * (size_t)ldC + col,
                                        fc[mi][ni], ldC, wmma::mem_row_major);
            }
    } else {
        for (int mi = 0; mi < 2; mi++)
            for (int ni = 0; ni < 2; ni++)
                wmma::store_matrix_sync(sC + (wm*32 + mi*16)*72 + wn*32 + ni*16,
                                        fc[mi][ni], 72, wmma::mem_row_major);
        __syncthreads();

        // 2 threads per row handle halves of the 64 cols
        int r  = tid >> 1;
        int hf = tid & 1;
        float* crow = sC + r*72 + hf*32;
        float mx = -1e30f;
        for (int c = 0; c < 32; c++) {
            int gc = bn + hf*32 + c;
            float v = (gc < Ncols) ? (crow[c] + bias[gc]) : -1e30f;
            crow[c] = v;
            mx = fmaxf(mx, v);
        }
        float s = 0.0f;
        for (int c = 0; c < 32; c++) s += expf(crow[c] - mx);

        float mo = __shfl_xor_sync(0xffffffffu, mx, 1);
        float so = __shfl_xor_sync(0xffffffffu, s,  1);
        float M = fmaxf(mx, mo);
        float S = s * expf(mx - M) + so * expf(mo - M);

        int rg = bm + r;
        int tv = tgt[rg];
        int lc = tv - bn - hf*32;
        if (lc >= 0 && lc < 32) g_tgtlog[rg] = crow[lc];
        if (hf == 0) {
            g_pm[(size_t)rg * NCB + blockIdx.x] = M;
            g_ps[(size_t)rg * NCB + blockIdx.x] = S;
        }
    }
}

// ---------------- generic fp32 SGEMM (small phase-A ops) ----------------
template<bool GATHER>
__global__ void __launch_bounds__(256)
k_sgemm128(const float* __restrict__ A,
           const int*  __restrict__ gidx,
           const float* __restrict__ Bw, int ldb,
           const float* __restrict__ bias,
           float* __restrict__ C,
           int M, int N, int K)
{
    __shared__ __align__(16) float sA[16][128];
    __shared__ __align__(16) float sB[16][128];
    const int tid = threadIdx.x;
    const int bm = blockIdx.y * 128;
    const int bn = blockIdx.x * 128;
    const int tx = tid & 15;
    const int ty = tid >> 4;
    const int lr = tid >> 2;
    const int lk = (tid & 3) << 2;

    int m0 = bm + lr, m1 = m0 + 64;
    const bool mv0 = m0 < M, mv1 = m1 < M;
    size_t ar0, ar1;
    if (GATHER) {
        ar0 = (size_t)(mv0 ? gidx[m0] : gidx[0]) * (size_t)K;
        ar1 = (size_t)(mv1 ? gidx[m1] : gidx[0]) * (size_t)K;
    } else {
        ar0 = (size_t)(mv0 ? m0 : 0) * (size_t)K;
        ar1 = (size_t)(mv1 ? m1 : 0) * (size_t)K;
    }
    int n0 = bn + lr, n1 = n0 + 64;
    size_t br0 = (size_t)(n0 < N ? n0 : 0) * (size_t)ldb;
    size_t br1 = (size_t)(n1 < N ? n1 : 0) * (size_t)ldb;

    float acc[8][8];
#pragma unroll
    for (int i = 0; i < 8; i++)
#pragma unroll
        for (int j = 0; j < 8; j++) acc[i][j] = 0.0f;

    for (int kb = 0; kb < K; kb += 16) {
        float4 a0 = *(const float4*)(A  + ar0 + kb + lk);
        float4 a1 = *(const float4*)(A  + ar1 + kb + lk);
        float4 b0 = *(const float4*)(Bw + br0 + kb + lk);
        float4 b1 = *(const float4*)(Bw + br1 + kb + lk);
        __syncthreads();
        sA[lk+0][lr] = a0.x; sA[lk+1][lr] = a0.y; sA[lk+2][lr] = a0.z; sA[lk+3][lr] = a0.w;
        sA[lk+0][lr+64] = a1.x; sA[lk+1][lr+64] = a1.y; sA[lk+2][lr+64] = a1.z; sA[lk+3][lr+64] = a1.w;
        sB[lk+0][lr] = b0.x; sB[lk+1][lr] = b0.y; sB[lk+2][lr] = b0.z; sB[lk+3][lr] = b0.w;
        sB[lk+0][lr+64] = b1.x; sB[lk+1][lr+64] = b1.y; sB[lk+2][lr+64] = b1.z; sB[lk+3][lr+64] = b1.w;
        __syncthreads();
#pragma unroll
        for (int k = 0; k < 16; k++) {
            float4 pa0 = *(const float4*)(&sA[k][ty*8]);
            float4 pa1 = *(const float4*)(&sA[k][ty*8+4]);
            float4 pb0 = *(const float4*)(&sB[k][tx*8]);
            float4 pb1 = *(const float4*)(&sB[k][tx*8+4]);
            float av[8] = {pa0.x, pa0.y, pa0.z, pa0.w, pa1.x, pa1.y, pa1.z, pa1.w};
            float bv[8] = {pb0.x, pb0.y, pb0.z, pb0.w, pb1.x, pb1.y, pb1.z, pb1.w};
#pragma unroll
            for (int i = 0; i < 8; i++)
#pragma unroll
                for (int j = 0; j < 8; j++)
                    acc[i][j] += av[i] * bv[j];
        }
    }

#pragma unroll
    for (int i = 0; i < 8; i++) {
        int m = bm + ty*8 + i;
        if (m < M) {
            float* crow = C + (size_t)m * (size_t)N;
#pragma unroll
            for (int j = 0; j < 8; j++) {
                int n = bn + tx*8 + j;
                if (n < N) crow[n] = acc[i][j] + (bias ? bias[n] : 0.0f);
            }
        }
    }
}

// ---------------- per-task 64x64 WMMA step-GEMM (bf16 in, fp32 out) ----------------
// C tile [64 x 64] at column bn: Cp[row*G3 + bn + col] += A[row, kbase:kbase+256] @ B[bn+col, ...]^T
__device__ __forceinline__ void step_wmma_task(
    const __nv_bfloat16* __restrict__ A, const __nv_bfloat16* __restrict__ B,
    int bn, int kbase, float* __restrict__ Cp, char* sbuf)
{
    __nv_bfloat16* sA = (__nv_bfloat16*)sbuf;             // 64 x 40
    __nv_bfloat16* sB = (__nv_bfloat16*)(sbuf + 5120);    // 64 x 40
    const int tid  = threadIdx.x;
    const int warp = tid >> 5;
    const int wm = warp >> 2;        // 0..1  (M halves of 32)
    const int wn = warp & 3;         // 0..3  (N quarters of 16)
    const int cr = tid >> 2;         // 0..63
    const int ck = (tid & 3) << 3;   // 0,8,16,24

    size_t aoff = (size_t)cr * HID + kbase + ck;
    size_t boff = (size_t)(bn + cr) * HID + kbase + ck;
    const int si = cr*40 + ck;

    wmma::fragment<wmma::accumulator, 16, 16, 16, float> fc0, fc1;
    wmma::fill_fragment(fc0, 0.0f);
    wmma::fill_fragment(fc1, 0.0f);

    for (int it = 0; it < 8; it++) {
        __syncthreads();
        *(uint4*)(sA + si) = *(const uint4*)(A + aoff + it*32);
        *(uint4*)(sB + si) = *(const uint4*)(B + boff + it*32);
        __syncthreads();
        for (int kk = 0; kk < 32; kk += 16) {
            wmma::fragment<wmma::matrix_a, 16, 16, 16, __nv_bfloat16, wmma::row_major> fa0, fa1;
            wmma::fragment<wmma::matrix_b, 16, 16, 16, __nv_bfloat16, wmma::col_major> fb;
            wmma::load_matrix_sync(fa0, sA + (wm*32     )*40 + kk, 40);
            wmma::load_matrix_sync(fa1, sA + (wm*32 + 16)*40 + kk, 40);
            wmma::load_matrix_sync(fb,  sB + (wn*16     )*40 + kk, 40);
            wmma::mma_sync(fc0, fa0, fb, fc0);
            wmma::mma_sync(fc1, fa1, fb, fc1);
        }
    }
    wmma::store_matrix_sync(Cp + (size_t)(wm*32     )*G3 + bn + wn*16, fc0, G3, wmma::mem_row_major);
    wmma::store_matrix_sync(Cp + (size_t)(wm*32 + 16)*G3 + bn + wn*16, fc1, G3, wmma::mem_row_major);
}

// ---------------- persistent encoder ----------------
__global__ void __launch_bounds__(256)
k_encoder(const float* __restrict__ bih, const float* __restrict__ bhh)
{
    __shared__ __align__(16) char sbuf[12288];
    unsigned gen = 0;
    if (threadIdx.x == 0) gen = atomicAdd(&g_bargen, 0u);
    const int blk = blockIdx.x;

    for (int t = 0; t < LEN; t++) {
        // h @ Whh^T via tensor cores: 2 K-splits x 24 n-tiles = 48 tasks
        if (blk < 48) {
            int ks = blk / 24, nb = blk % 24;
            step_wmma_task(g_hbf, g_Whhbf, nb*64, ks*256, g_part + (size_t)ks*BSZ*G3, sbuf);
        }
        gridbar(gen);
        if (blk < 128) {
            int idx = blk*256 + threadIdx.x;
            int b = idx >> 9, j = idx & 511;
            int base = b * G3;
            float hr = bhh[j], hz = bhh[j+512], hn = bhh[j+1024];
#pragma unroll
            for (int s = 0; s < 2; s++) {
                const float* p = g_part + (size_t)s * BSZ * G3 + base;
                hr += p[j]; hz += p[j+512]; hn += p[j+1024];
            }
            const float* gx = g_encGx + ((size_t)t*BSZ + b) * G3;
            float r = sigmf(gx[j] + bih[j] + hr);
            float z = sigmf(gx[j+512] + bih[j+512] + hz);
            float n = tanhf(gx[j+1024] + bih[j+1024] + r * hn);
            float hp = g_h[idx];
            float h2 = (1.0f - z) * n + z * hp;
            g_h[idx] = h2;
            g_hbf[idx] = __float2bfloat16(h2);
            if (t == 0) g_enc0[idx] = h2;
        }
        gridbar(gen);
    }
}

// ---------------- persistent decoder ----------------
__global__ void __launch_bounds__(256)
k_decoder(const float* __restrict__ attn_W,
          const float* __restrict__ bih, const float* __restrict__ bhh)
{
    __shared__ __align__(16) char sbuf[12288];
    float* sm = (float*)sbuf;
    unsigned gen = 0;
    if (threadIdx.x == 0) gen = atomicAdd(&g_bargen, 0u);
    const int blk = blockIdx.x;
    const int tid = threadIdx.x;

    for (int t = 0; t < TOUT; t++) {
        // --- attention: a0[b] = softmax over LMAX of (attnx + h-part)[0]
        if (blk < 64) {
            const int b = blk;
            float* sh = sm;
            float* slg = sm + 512;
            float* sred = sm + 912;
            sh[tid]       = g_h[b*HID + tid];
            sh[tid + 256] = g_h[b*HID + tid + 256];
            __syncthreads();
            const float4* h4 = (const float4*)sh;
            for (int l = tid; l < LMAX; l += 256) {
                const float4* w4 = (const float4*)(attn_W + (size_t)l*1024 + 512);
                float s = 0.0f;
#pragma unroll 4
                for (int k = 0; k < 128; k++) {
                    float4 w = w4[k], h = h4[k];
                    s += w.x*h.x + w.y*h.y + w.z*h.z + w.w*h.w;
                }
                slg[l] = g_attnx[((size_t)t*BSZ + b)*LMAX + l] + s;
            }
            __syncthreads();
            float lm = -1e30f;
            for (int l = tid; l < LMAX; l += 256) lm = fmaxf(lm, slg[l]);
            sred[tid] = lm; __syncthreads();
            for (int off = 128; off > 0; off >>= 1) {
                if (tid < off) sred[tid] = fmaxf(sred[tid], sred[tid+off]);
                __syncthreads();
            }
            float mx = sred[0];
            __syncthreads();
            float ls = 0.0f;
            for (int l = tid; l < LMAX; l += 256) ls += expf(slg[l] - mx);
            sred[tid] = ls; __syncthreads();
            for (int off = 128; off > 0; off >>= 1) {
                if (tid < off) sred[tid] += sred[tid+off];
                __syncthreads();
            }
            if (tid == 0) g_a0[b] = expf(slg[0] - mx) / sred[0];
        }
        gridbar(gen);
        // --- combine: c = relu(combx + a0*enc0W), stored bf16
        if (blk < 128) {
            int idx = blk*256 + tid;
            int b = idx >> 9, j = idx & 511;
            float v = g_combx[((size_t)t*BSZ + b)*HID + j] + g_a0[b] * g_enc0W[idx];
            g_cbf[idx] = __float2bfloat16(v > 0.0f ? v : 0.0f);
        }
        gridbar(gen);
        // --- two GEMMs via tensor cores: {c@Wih, h@Whh} x 2 K-splits x 24 tiles = 96 tasks
        if (blk < 96) {
            int group = blk / 48, rem = blk % 48;
            int ks = rem / 24, nb = rem % 24;
            const __nv_bfloat16* A  = group ? g_hbf : g_cbf;
            const __nv_bfloat16* Bm = group ? g_dWhhbf : g_dWihbf;
            step_wmma_task(A, Bm, nb*64, ks*256,
                           g_part + (size_t)(group*2 + ks)*BSZ*G3, sbuf);
        }
        gridbar(gen);
        // --- gate fuse (writes g_h, g_hbf, g_H2bf)
        if (blk < 128) {
            int idx = blk*256 + tid;
            int b = idx >> 9, j = idx & 511;
            int base = b * G3;
            float ir = bih[j], iz = bih[j+512], in = bih[j+1024];
            float hr = bhh[j], hz = bhh[j+512], hn = bhh[j+1024];
#pragma unroll
            for (int s = 0; s < 2; s++) {
                const float* pi = g_part + (size_t)s * BSZ * G3 + base;
                const float* ph = g_part + (size_t)(s+2) * BSZ * G3 + base;
                ir += pi[j]; iz += pi[j+512]; in += pi[j+1024];
                hr += ph[j]; hz += ph[j+512]; hn += ph[j+1024];
            }
            float r = sigmf(ir + hr);
            float z = sigmf(iz + hz);
            float n = tanhf(in + r * hn);
            float hp = g_h[idx];
            float h2 = (1.0f - z) * n + z * hp;
            g_h[idx] = h2;
            g_hbf[idx] = __float2bfloat16(h2);
            g_H2bf[(size_t)t*BSZ*HID + idx] = __float2bfloat16(h2);
        }
        gridbar(gen);
    }
}

// ---------------- final logsumexp combine + deterministic loss ----------------
__global__ void k_reduce()
{
    __shared__ float sred[256];
    int m = blockIdx.x * 256 + threadIdx.x;   // 25*256 = 6400 exactly
    const float* pm = g_pm + (size_t)m * NCB;
    const float* ps = g_ps + (size_t)m * NCB;
    float M = pm[0];
    for (int j = 1; j < NCB; j++) M = fmaxf(M, pm[j]);
    float S = 0.0f;
    for (int j = 0; j < NCB; j++) S += ps[j] * expf(pm[j] - M);
    float contrib = (M + logf(S) - g_tgtlog[m]) * (1.0f / 64.0f);
    sred[threadIdx.x] = contrib;
    __syncthreads();
    for (int off = 128; off > 0; off >>= 1) {
        if (threadIdx.x < off) sred[threadIdx.x] += sred[threadIdx.x + off];
        __syncthreads();
    }
    if (threadIdx.x == 0) g_lossp[blockIdx.x] = sred[0];
}

__global__ void k_final(float* __restrict__ out)
{
    float s = 0.0f;
    for (int i = 0; i < 25; i++) s += g_lossp[i];
    out[0] = s;
}

// ---------------- host launcher ----------------
extern "C" void kernel_launch(void* const* d_in, const int* in_sizes, int n_in,
                              void* d_out, int out_size)
{
    const float* emb     = (const float*)d_in[0];
    const float* enc_Wih = (const float*)d_in[1];
    const float* enc_Whh = (const float*)d_in[2];
    const float* enc_bih = (const float*)d_in[3];
    const float* enc_bhh = (const float*)d_in[4];
    const float* attn_W  = (const float*)d_in[5];
    const float* attn_b  = (const float*)d_in[6];
    const float* comb_W  = (const float*)d_in[7];
    const float* comb_b  = (const float*)d_in[8];
    const float* dec_Wih = (const float*)d_in[9];
    const float* dec_Whh = (const float*)d_in[10];
    const float* dec_bih = (const float*)d_in[11];
    const float* dec_bhh = (const float*)d_in[12];
    const float* out_W   = (const float*)d_in[13];
    const float* out_b   = (const float*)d_in[14];
    const int*   in_tok  = (const int*)d_in[15];
    const int*   tgt     = (const int*)d_in[16];

    float *p_attnx, *p_combx, *p_enc0, *p_enc0W, *p_encGx;
    int *p_dectok;
    __nv_bfloat16 *p_embbf, *p_Wobf, *p_Wihbf, *p_Whhbf, *p_dWihbf, *p_dWhhbf, *p_H2bf;
    cudaGetSymbolAddress((void**)&p_encGx, g_encGx);
    cudaGetSymbolAddress((void**)&p_attnx, g_attnx);
    cudaGetSymbolAddress((void**)&p_combx, g_combx);
    cudaGetSymbolAddress((void**)&p_enc0,  g_enc0);
    cudaGetSymbolAddress((void**)&p_enc0W, g_enc0W);
    cudaGetSymbolAddress((void**)&p_dectok, g_dectok);
    cudaGetSymbolAddress((void**)&p_embbf, g_embbf);
    cudaGetSymbolAddress((void**)&p_Wobf,  g_Wobf);
    cudaGetSymbolAddress((void**)&p_Wihbf, g_Wihbf);
    cudaGetSymbolAddress((void**)&p_Whhbf, g_Whhbf);
    cudaGetSymbolAddress((void**)&p_dWihbf, g_dWihbf);
    cudaGetSymbolAddress((void**)&p_dWhhbf, g_dWhhbf);
    cudaGetSymbolAddress((void**)&p_H2bf,  g_H2bf);

    // init + bf16 conversions
    k_init<<<128, 256>>>(tgt);
    k_tobf<<<(VOC*HID)/1024, 256>>>(emb,     p_embbf, VOC*HID);
    k_tobf<<<(VOC*HID)/1024, 256>>>(out_W,   p_Wobf,  VOC*HID);
    k_tobf<<<(G3*HID)/1024,  256>>>(enc_Wih, p_Wihbf, G3*HID);
    k_tobf<<<(G3*HID)/1024,  256>>>(enc_Whh, p_Whhbf, G3*HID);
    k_tobf<<<(G3*HID)/1024,  256>>>(dec_Wih, p_dWihbf, G3*HID);
    k_tobf<<<(G3*HID)/1024,  256>>>(dec_Whh, p_dWhhbf, G3*HID);

    // phase A: encGx via WMMA bf16 (token gather fused; bias added in encoder fuse)
    k_wgemm<0><<<dim3(24, 200), 256>>>(p_embbf, in_tok, p_Wihbf,
                                       (const float*)0, p_encGx, G3,
                                       (const int*)0, G3);
    // small fp32 GEMMs for decoder x-parts
    k_sgemm128<true><<<dim3(4, 50), 256>>>(emb, p_dectok, attn_W, 1024, attn_b, p_attnx, MROWS, LMAX, HID);
    k_sgemm128<true><<<dim3(4, 50), 256>>>(emb, p_dectok, comb_W, 1024, comb_b, p_combx, MROWS, HID,  HID);

    // phase B1: persistent encoder
    k_encoder<<<NBLK, 256>>>(enc_bih, enc_bhh);

    // enc0W = enc0 @ comb_W[:, H:]^T
    k_sgemm128<false><<<dim3(4, 1), 256>>>(p_enc0, (const int*)0, comb_W + 512, 1024,
                                           (const float*)0, p_enc0W, BSZ, HID, HID);

    // phase B2: persistent decoder
    k_decoder<<<NBLK, 256>>>(attn_W, dec_bih, dec_bhh);

    // phase C: WMMA bf16 projection with fused logsumexp partials
    k_wgemm<1><<<dim3(NCB, 50), 256>>>(p_H2bf, (const int*)0, p_Wobf, out_b,
                                       (float*)0, 0, tgt, VOC);
    k_reduce<<<25, 256>>>();
    k_final<<<1, 1>>>((float*)d_out);
}